// round 14
// baseline (speedup 1.0000x reference)
#include <cuda_runtime.h>
#include <cstdint>
#include <math.h>

#define NB  512
#define NN  32
#define DSA 64
#define DH  128
#define PITCH 34   // floats/row, even -> 8B-aligned u64 pairs

typedef unsigned long long u64;
typedef unsigned int u32;
#define ABSM  0x7fffffff7fffffffULL

// ---------- f32x2 helpers ----------
__device__ __forceinline__ u64 f2_fma(u64 a, u64 b, u64 c) {
    u64 d; asm("fma.rn.f32x2 %0,%1,%2,%3;" : "=l"(d) : "l"(a), "l"(b), "l"(c)); return d;
}
__device__ __forceinline__ u64 f2_add(u64 a, u64 b) {
    u64 d; asm("add.rn.f32x2 %0,%1,%2;" : "=l"(d) : "l"(a), "l"(b)); return d;
}
__device__ __forceinline__ u64 f2_pack(float lo, float hi) {
    u64 d; asm("mov.b64 %0,{%1,%2};" : "=l"(d) : "f"(lo), "f"(hi)); return d;
}
__device__ __forceinline__ float2 f2_unpack(u64 a) {
    float2 r; asm("mov.b64 {%0,%1},%2;" : "=f"(r.x), "=f"(r.y) : "l"(a)); return r;
}

// ---------- cp.async helpers ----------
__device__ __forceinline__ void cpa16(u32 dst, const float* src) {
    asm volatile("cp.async.cg.shared.global [%0], [%1], 16;\n" :: "r"(dst), "l"(src));
}
__device__ __forceinline__ void cpa_commit() {
    asm volatile("cp.async.commit_group;\n");
}
__device__ __forceinline__ void cpa_wait1() {
    asm volatile("cp.async.wait_group 1;\n");
}
__device__ __forceinline__ void cpa_wait0() {
    asm volatile("cp.async.wait_group 0;\n");
}

// Transposed float weights: Wt[k][h] (h contiguous).
__device__ float g_Wt_msg1[128 * DH];
__device__ float g_Wt_msg2[256 * DH];
__device__ float g_Wt_up1 [192 * DH];
__device__ float g_Wt_up2 [192 * DH];

__global__ void prep_weights_kernel(const float* __restrict__ Wm1,
                                    const float* __restrict__ Wm2,
                                    const float* __restrict__ Wu1,
                                    const float* __restrict__ Wu2) {
    const int stride = gridDim.x * blockDim.x;
    const int t0 = blockIdx.x * blockDim.x + threadIdx.x;
    for (int i = t0; i < DH * 128; i += stride) {
        int h = i >> 7, k = i & 127;
        g_Wt_msg1[k * DH + h] = Wm1[i];
    }
    for (int i = t0; i < DH * 256; i += stride) {
        int h = i >> 8, k = i & 255;
        g_Wt_msg2[k * DH + h] = Wm2[i];
    }
    for (int i = t0; i < DH * 192; i += stride) {
        int h = i / 192, k = i % 192;
        g_Wt_up1[k * DH + h] = Wu1[i];
        g_Wt_up2[k * DH + h] = Wu2[i];
    }
}

// ---- staging: msg chunk = 8 rows of Wl + 8 rows of Wr (2048 floats = 8 KB) ----
__device__ __forceinline__ void stage_msg(u32 dst, const float* Wl,
                                          const float* Wr, int k0, int tid) {
    #pragma unroll
    for (int t = 0; t < 2; t++) {
        int i = tid + t * 128;                 // 256 xfers per stream
        cpa16(dst + i * 16,        Wl + k0 * DH + i * 4);
        cpa16(dst + 4096 + i * 16, Wr + k0 * DH + i * 4);
    }
}
// ---- staging: update chunk = 16 rows (2048 floats = 8 KB) ----
__device__ __forceinline__ void stage_up(u32 dst, const float* W, int k0, int tid) {
    #pragma unroll
    for (int t = 0; t < 4; t++) {
        int i = tid + t * 128;
        cpa16(dst + i * 16, W + k0 * DH + i * 4);
    }
}

// ---- compute: 8 k's of a msg GEMM from staged weights (LDS.64 act reads) ----
__device__ __forceinline__ void msg_chunk(u64* accA, u64* accB, const float* wb,
                                          const float* act, int h) {
    #pragma unroll
    for (int kk = 0; kk < 8; kk++) {
        float wl = wb[kk * DH + h];
        float wr = wb[1024 + kk * DH + h];
        u64 wl2 = f2_pack(wl, wl), wr2 = f2_pack(wr, wr);
        const u64* ar = reinterpret_cast<const u64*>(act + kk * PITCH);
        #pragma unroll
        for (int q = 0; q < 16; q++) {
            u64 a = ar[q];
            accA[q] = f2_fma(a, wl2, accA[q]);
            accB[q] = f2_fma(a, wr2, accB[q]);
        }
    }
}
// ---- compute: 16 k's of an update GEMM, h-paired: each act LDS.64 feeds
//      BOTH h0 and h1 -> act wavefronts halve vs one-h-per-thread ----
__device__ __forceinline__ void up_chunk(u64* v0, u64* v1, const float* wb,
                                         const float* act, int h0, int ioff) {
    #pragma unroll
    for (int kk = 0; kk < 16; kk++) {
        float2 wp = *reinterpret_cast<const float2*>(wb + kk * DH + h0);
        u64 w0 = f2_pack(wp.x, wp.x), w1 = f2_pack(wp.y, wp.y);
        const u64* ar = reinterpret_cast<const u64*>(act + kk * PITCH + ioff);
        #pragma unroll
        for (int q = 0; q < 8; q++) {
            u64 a = ar[q];
            v0[q] = f2_fma(a, w0, v0[q]);
            v1[q] = f2_fma(a, w1, v1[q]);
        }
    }
}

__global__ void __launch_bounds__(128, 4)
msggraph_kernel(const float* __restrict__ x,
                const float* __restrict__ bm1,
                const float* __restrict__ bm2,
                const float* __restrict__ bu1,
                const float* __restrict__ bu2,
                const float* __restrict__ Wv,
                const float* __restrict__ bv,
                float* __restrict__ out)
{
    __shared__ __align__(16) float xsT[DSA * PITCH];   // [k][j]
    __shared__ __align__(16) float PT [DH  * PITCH];   // [k][i]: agg1 -> v1 -> agg2
    __shared__ __align__(16) float ws[2][2048];        // weight double-buffer (16 KB)
    __shared__ float mxs[2 * DH];
    __shared__ float red[4];

    const int tid = threadIdx.x;
    const int h   = tid;               // msg phase: thread = output channel
    const int b   = blockIdx.x;
    // up phase mapping: thread = (h-pair, i-half)
    const int hp   = tid & 63;
    const int ih   = tid >> 6;
    const int h0   = hp * 2;
    const int h1   = h0 + 1;
    const int ioff = ih * 16;
    const u32 wsa = (u32)__cvta_generic_to_shared(ws);

    // Load x[b] ([j=32][k=64] row-major) into transposed xsT[k][j].
    const float* xb = x + b * (NN * DSA);
    #pragma unroll
    for (int it = 0; it < 16; it++) {
        int idx = it * 128 + tid;
        xsT[(idx & 63) * PITCH + (idx >> 6)] = xb[idx];
    }

    u64 accA[16], accB[16];   // msg: all 32 j's as 16 packed pairs
    u64 v0[8], v1[8];         // up:  16 i's for h0 and h1

    // ---- driver macros ----
#define MSG_GEMM(WT, NK, ACT)                                                  \
    {                                                                          \
        _Pragma("unroll")                                                      \
        for (int q = 0; q < 16; q++) { accA[q] = 0; accB[q] = 0; }             \
        const float* Wl = (WT);                                                \
        const float* Wr = (WT) + (NK) * DH;                                    \
        const int NC = (NK) >> 3;                                              \
        stage_msg(wsa, Wl, Wr, 0, tid); cpa_commit();                          \
        for (int c = 0; c < NC; c++) {                                         \
            if (c + 1 < NC) {                                                  \
                stage_msg(wsa + ((c + 1) & 1) * 8192, Wl, Wr, (c + 1) * 8, tid); \
                cpa_commit(); cpa_wait1();                                     \
            } else cpa_wait0();                                                \
            __syncthreads();                                                   \
            msg_chunk(accA, accB, ws[c & 1], (ACT) + (c * 8) * PITCH, h);      \
            __syncthreads();                                                   \
        }                                                                      \
    }

#define UP_GEMM(WT)                                                            \
    {                                                                          \
        _Pragma("unroll")                                                      \
        for (int q = 0; q < 8; q++) { v0[q] = 0; v1[q] = 0; }                  \
        stage_up(wsa, (WT), 0, tid); cpa_commit();                             \
        for (int c = 0; c < 12; c++) {                                         \
            if (c + 1 < 12) {                                                  \
                stage_up(wsa + ((c + 1) & 1) * 8192, (WT), (c + 1) * 16, tid); \
                cpa_commit(); cpa_wait1();                                     \
            } else cpa_wait0();                                                \
            __syncthreads();                                                   \
            const float* act = (c < 4) ? (xsT + c * 16 * PITCH)                \
                                       : (PT + (c * 16 - 64) * PITCH);         \
            up_chunk(v0, v1, ws[c & 1], act, h0, ioff);                        \
            __syncthreads();                                                   \
        }                                                                      \
    }

    // agg[i] = 0.5*(SA + 32*B_i + sum_j |A_j+B_i|) - relu(A_i+B_i)
#define MSG_EPI(BM)                                                            \
    {                                                                          \
        float bm = (BM)[h];                                                    \
        u64 bmp = f2_pack(bm, bm);                                             \
        _Pragma("unroll")                                                      \
        for (int j2 = 0; j2 < 16; j2++) accA[j2] = f2_add(accA[j2], bmp);      \
        u64 sAp = accA[0];                                                     \
        _Pragma("unroll")                                                      \
        for (int j2 = 1; j2 < 16; j2++) sAp = f2_add(sAp, accA[j2]);           \
        float2 sAf = f2_unpack(sAp);                                           \
        float SA = sAf.x + sAf.y;                                              \
        _Pragma("unroll")                                                      \
        for (int i2 = 0; i2 < 16; i2++) {                                      \
            float2 B2 = f2_unpack(accB[i2]);                                   \
            u64 bx = f2_pack(B2.x, B2.x), by = f2_pack(B2.y, B2.y);            \
            u64 ax = 0, ay = 0;                                                \
            _Pragma("unroll")                                                  \
            for (int j2 = 0; j2 < 16; j2++) {                                  \
                u64 A = accA[j2];                                              \
                ax = f2_add(ax, f2_add(A, bx) & ABSM);                         \
                ay = f2_add(ay, f2_add(A, by) & ABSM);                         \
            }                                                                  \
            float2 axf = f2_unpack(ax), ayf = f2_unpack(ay);                   \
            float2 Ai = f2_unpack(accA[i2]);                                   \
            float gx = 0.5f * (fmaf(32.f, B2.x, SA) + axf.x + axf.y)           \
                       - fmaxf(Ai.x + B2.x, 0.f);                              \
            float gy = 0.5f * (fmaf(32.f, B2.y, SA) + ayf.x + ayf.y)           \
                       - fmaxf(Ai.y + B2.y, 0.f);                              \
            *reinterpret_cast<u64*>(&PT[h * PITCH + 2 * i2]) = f2_pack(gx, gy);\
        }                                                                      \
    }

    // ================= Layer 1 =================
    MSG_GEMM(g_Wt_msg1, DSA, xsT)
    MSG_EPI(bm1)                     // GEMM's trailing sync: all reads of xsT done
    __syncthreads();                 // PT(agg1) visible

    UP_GEMM(g_Wt_up1)                // trailing sync: all reads of PT(agg1) done
    {
        float bb0 = bu1[h0], bb1 = bu1[h1];
        u64 bp0 = f2_pack(bb0, bb0), bp1 = f2_pack(bb1, bb1);
        #pragma unroll
        for (int q = 0; q < 8; q++) {
            float2 t0 = f2_unpack(f2_add(v0[q], bp0));
            float2 t1 = f2_unpack(f2_add(v1[q], bp1));
            *reinterpret_cast<u64*>(&PT[h0 * PITCH + ioff + 2 * q]) =
                f2_pack(fmaxf(t0.x, 0.f), fmaxf(t0.y, 0.f));
            *reinterpret_cast<u64*>(&PT[h1 * PITCH + ioff + 2 * q]) =
                f2_pack(fmaxf(t1.x, 0.f), fmaxf(t1.y, 0.f));
        }
    }
    __syncthreads();                 // PT(v1) visible

    // ================= Layer 2 =================
    MSG_GEMM(g_Wt_msg2, DH, PT)      // trailing sync: all reads of PT(v1) done
    MSG_EPI(bm2)
    __syncthreads();                 // PT(agg2) visible

    UP_GEMM(g_Wt_up2)
    {
        float bb0 = bu2[h0], bb1 = bu2[h1];
        u64 bp0 = f2_pack(bb0, bb0), bp1 = f2_pack(bb1, bb1);
        float m0 = -INFINITY, m1 = -INFINITY;
        #pragma unroll
        for (int q = 0; q < 8; q++) {
            float2 t0 = f2_unpack(f2_add(v0[q], bp0));
            float2 t1 = f2_unpack(f2_add(v1[q], bp1));
            m0 = fmaxf(m0, fmaxf(t0.x, t0.y));
            m1 = fmaxf(m1, fmaxf(t1.x, t1.y));
        }
        mxs[ih * DH + h0] = fmaxf(m0, 0.f);   // relu-then-max == max-then-relu
        mxs[ih * DH + h1] = fmaxf(m1, 0.f);
    }
    __syncthreads();

    // out[b] = sum_h max-over-i(v2[i][h]) * Wv[h] + bv
    float m = fmaxf(mxs[tid], mxs[DH + tid]);
    float contrib = m * Wv[tid];
    #pragma unroll
    for (int o = 16; o; o >>= 1)
        contrib += __shfl_xor_sync(0xffffffffu, contrib, o);
    if ((tid & 31) == 0) red[tid >> 5] = contrib;
    __syncthreads();
    if (tid == 0) out[b] = red[0] + red[1] + red[2] + red[3] + bv[0];
}

extern "C" void kernel_launch(void* const* d_in, const int* in_sizes, int n_in,
                              void* d_out, int out_size) {
    const float* x   = (const float*)d_in[0];
    // d_in[1] = ext_adj (structure folded into the agg epilogue)
    const float* Wm1 = (const float*)d_in[2];
    const float* bm1 = (const float*)d_in[3];
    const float* Wm2 = (const float*)d_in[4];
    const float* bm2 = (const float*)d_in[5];
    const float* Wu1 = (const float*)d_in[6];
    const float* bu1 = (const float*)d_in[7];
    const float* Wu2 = (const float*)d_in[8];
    const float* bu2 = (const float*)d_in[9];
    const float* Wv  = (const float*)d_in[10];
    const float* bv  = (const float*)d_in[11];

    prep_weights_kernel<<<148, 256>>>(Wm1, Wm2, Wu1, Wu2);
    msggraph_kernel<<<NB, 128>>>(x, bm1, bm2, bu1, bu2, Wv, bv, (float*)d_out);
}

// round 15
// speedup vs baseline: 1.0256x; 1.0256x over previous
#include <cuda_runtime.h>
#include <cstdint>
#include <math.h>

#define NB  512
#define NN  32
#define DSA 64
#define DH  128
#define PITCH 34   // floats/row, even -> 8B-aligned u64 pairs

typedef unsigned long long u64;
typedef unsigned int u32;
#define ABSM  0x7fffffff7fffffffULL
#define SIGN2 0x8000000080000000ULL
#define HALF2 0x3F0000003F000000ULL

// ---------- f32x2 helpers ----------
__device__ __forceinline__ u64 f2_fma(u64 a, u64 b, u64 c) {
    u64 d; asm("fma.rn.f32x2 %0,%1,%2,%3;" : "=l"(d) : "l"(a), "l"(b), "l"(c)); return d;
}
__device__ __forceinline__ u64 f2_add(u64 a, u64 b) {
    u64 d; asm("add.rn.f32x2 %0,%1,%2;" : "=l"(d) : "l"(a), "l"(b)); return d;
}
__device__ __forceinline__ u64 f2_mul(u64 a, u64 b) {
    u64 d; asm("mul.rn.f32x2 %0,%1,%2;" : "=l"(d) : "l"(a), "l"(b)); return d;
}
__device__ __forceinline__ u64 f2_pack(float lo, float hi) {
    u64 d; asm("mov.b64 %0,{%1,%2};" : "=l"(d) : "f"(lo), "f"(hi)); return d;
}
__device__ __forceinline__ float2 f2_unpack(u64 a) {
    float2 r; asm("mov.b64 {%0,%1},%2;" : "=f"(r.x), "=f"(r.y) : "l"(a)); return r;
}

// ---------- cp.async helpers ----------
__device__ __forceinline__ void cpa16(u32 dst, const float* src) {
    asm volatile("cp.async.cg.shared.global [%0], [%1], 16;\n" :: "r"(dst), "l"(src));
}
__device__ __forceinline__ void cpa_commit() {
    asm volatile("cp.async.commit_group;\n");
}
__device__ __forceinline__ void cpa_wait1() {
    asm volatile("cp.async.wait_group 1;\n");
}
__device__ __forceinline__ void cpa_wait0() {
    asm volatile("cp.async.wait_group 0;\n");
}

// Transposed float weights: Wt[k][h] (h contiguous).
__device__ float g_Wt_msg1[128 * DH];
__device__ float g_Wt_msg2[256 * DH];
__device__ float g_Wt_up1 [192 * DH];
__device__ float g_Wt_up2 [192 * DH];

__global__ void prep_weights_kernel(const float* __restrict__ Wm1,
                                    const float* __restrict__ Wm2,
                                    const float* __restrict__ Wu1,
                                    const float* __restrict__ Wu2) {
    const int stride = gridDim.x * blockDim.x;
    const int t0 = blockIdx.x * blockDim.x + threadIdx.x;
    for (int i = t0; i < DH * 128; i += stride) {
        int h = i >> 7, k = i & 127;
        g_Wt_msg1[k * DH + h] = Wm1[i];
    }
    for (int i = t0; i < DH * 256; i += stride) {
        int h = i >> 8, k = i & 255;
        g_Wt_msg2[k * DH + h] = Wm2[i];
    }
    for (int i = t0; i < DH * 192; i += stride) {
        int h = i / 192, k = i % 192;
        g_Wt_up1[k * DH + h] = Wu1[i];
        g_Wt_up2[k * DH + h] = Wu2[i];
    }
}

// ---- staging: msg chunk = 8 rows of Wl + 8 rows of Wr (2048 floats = 8 KB) ----
__device__ __forceinline__ void stage_msg(u32 dst, const float* Wl,
                                          const float* Wr, int k0, int tid) {
    #pragma unroll
    for (int t = 0; t < 2; t++) {
        int i = tid + t * 128;                 // 256 xfers per stream
        cpa16(dst + i * 16,        Wl + k0 * DH + i * 4);
        cpa16(dst + 4096 + i * 16, Wr + k0 * DH + i * 4);
    }
}
// ---- staging: update chunk = 16 rows (2048 floats = 8 KB) ----
__device__ __forceinline__ void stage_up(u32 dst, const float* W, int k0, int tid) {
    #pragma unroll
    for (int t = 0; t < 4; t++) {
        int i = tid + t * 128;
        cpa16(dst + i * 16, W + k0 * DH + i * 4);
    }
}

// ---- compute: 8 k's of a msg GEMM, h-paired: each act LDS.64 feeds A and B
//      for BOTH h0 and h1 over this thread's 16 j's ----
__device__ __forceinline__ void msg_chunk(u64* aA0, u64* aA1, u64* aB0, u64* aB1,
                                          const float* wb, const float* act,
                                          int h0, int jbase) {
    #pragma unroll
    for (int kk = 0; kk < 8; kk++) {
        float2 wl = *reinterpret_cast<const float2*>(wb + kk * DH + h0);
        float2 wr = *reinterpret_cast<const float2*>(wb + 1024 + kk * DH + h0);
        u64 wl0 = f2_pack(wl.x, wl.x), wl1 = f2_pack(wl.y, wl.y);
        u64 wr0 = f2_pack(wr.x, wr.x), wr1 = f2_pack(wr.y, wr.y);
        const u64* ar = reinterpret_cast<const u64*>(act + kk * PITCH) + jbase;
        #pragma unroll
        for (int q = 0; q < 8; q++) {
            u64 a = ar[q];
            aA0[q] = f2_fma(a, wl0, aA0[q]);
            aA1[q] = f2_fma(a, wl1, aA1[q]);
            aB0[q] = f2_fma(a, wr0, aB0[q]);
            aB1[q] = f2_fma(a, wr1, aB1[q]);
        }
    }
}
// ---- compute: 16 k's of an update GEMM, h-paired (R14) ----
__device__ __forceinline__ void up_chunk(u64* v0, u64* v1, const float* wb,
                                         const float* act, int h0, int ioff) {
    #pragma unroll
    for (int kk = 0; kk < 16; kk++) {
        float2 wp = *reinterpret_cast<const float2*>(wb + kk * DH + h0);
        u64 w0 = f2_pack(wp.x, wp.x), w1 = f2_pack(wp.y, wp.y);
        const u64* ar = reinterpret_cast<const u64*>(act + kk * PITCH + ioff);
        #pragma unroll
        for (int q = 0; q < 8; q++) {
            u64 a = ar[q];
            v0[q] = f2_fma(a, w0, v0[q]);
            v1[q] = f2_fma(a, w1, v1[q]);
        }
    }
}

__global__ void __launch_bounds__(128, 4)
msggraph_kernel(const float* __restrict__ x,
                const float* __restrict__ bm1,
                const float* __restrict__ bm2,
                const float* __restrict__ bu1,
                const float* __restrict__ bu2,
                const float* __restrict__ Wv,
                const float* __restrict__ bv,
                float* __restrict__ out)
{
    __shared__ __align__(16) float xsT[DSA * PITCH];   // [k][j]
    __shared__ __align__(16) float PT [DH  * PITCH];   // [k][i]: agg1 -> v1 -> agg2
    __shared__ __align__(16) float ws[2][2048];        // weight dbl-buffer; reused as
                                                       // Bex (lower 8KB) / Pex (upper)
    __shared__ float mxs[2 * DH];
    __shared__ float red[4];

    const int tid = threadIdx.x;
    const int b   = blockIdx.x;
    // unified (h-pair, half) mapping for msg AND up phases
    const int hp    = tid & 63;     // h-pair
    const int jh    = tid >> 6;     // j/i half
    const int h0    = hp * 2;
    const int h1    = h0 + 1;
    const int jbase = jh * 8;       // u64 index of my 8 j-pairs
    const int ioff  = jh * 16;      // float offset of my 16 i's
    const u32 wsa = (u32)__cvta_generic_to_shared(ws);
    u64* Bex = reinterpret_cast<u64*>(&ws[0][0]);   // [i2=16][hp=64]
    u64* Pex = Bex + 1024;                          // [i2=16][hp=64]

    // Load x[b] ([j=32][k=64] row-major) into transposed xsT[k][j].
    const float* xb = x + b * (NN * DSA);
    #pragma unroll
    for (int it = 0; it < 16; it++) {
        int idx = it * 128 + tid;
        xsT[(idx & 63) * PITCH + (idx >> 6)] = xb[idx];
    }

    u64 aA0[8], aA1[8], aB0[8], aB1[8];   // msg: A,B for h0,h1 over my 16 j's
    u64 v0[8], v1[8];                     // up:  16 i's for h0,h1

#define MSG_GEMM(WT, NK, ACT)                                                  \
    {                                                                          \
        _Pragma("unroll")                                                      \
        for (int q = 0; q < 8; q++) { aA0[q]=0; aA1[q]=0; aB0[q]=0; aB1[q]=0; }\
        const float* Wl = (WT);                                                \
        const float* Wr = (WT) + (NK) * DH;                                    \
        const int NC = (NK) >> 3;                                              \
        stage_msg(wsa, Wl, Wr, 0, tid); cpa_commit();                          \
        for (int c = 0; c < NC; c++) {                                         \
            if (c + 1 < NC) {                                                  \
                stage_msg(wsa + ((c + 1) & 1) * 8192, Wl, Wr, (c + 1) * 8, tid); \
                cpa_commit(); cpa_wait1();                                     \
            } else cpa_wait0();                                                \
            __syncthreads();                                                   \
            msg_chunk(aA0, aA1, aB0, aB1, ws[c & 1],                           \
                      (ACT) + (c * 8) * PITCH, h0, jbase);                     \
            __syncthreads();                                                   \
        }                                                                      \
    }

#define UP_GEMM(WT)                                                            \
    {                                                                          \
        _Pragma("unroll")                                                      \
        for (int q = 0; q < 8; q++) { v0[q] = 0; v1[q] = 0; }                  \
        stage_up(wsa, (WT), 0, tid); cpa_commit();                             \
        for (int c = 0; c < 12; c++) {                                         \
            if (c + 1 < 12) {                                                  \
                stage_up(wsa + ((c + 1) & 1) * 8192, (WT), (c + 1) * 16, tid); \
                cpa_commit(); cpa_wait1();                                     \
            } else cpa_wait0();                                                \
            __syncthreads();                                                   \
            const float* act = (c < 4) ? (xsT + c * 16 * PITCH)                \
                                       : (PT + (c * 16 - 64) * PITCH);         \
            up_chunk(v0, v1, ws[c & 1], act, h0, ioff);                        \
            __syncthreads();                                                   \
        }                                                                      \
    }

    // ---- per-hs msg epilogue: B-exchange, split-j partials, combine ----
    // agg[i] = 0.5*(SA + 32*B_i + sum_j |A_j+B_i| - 2*relu(A_i+B_i))
    // partial(jh) = SA_half + sum_{my j} |A_j+B_i| (+32*B_i if jh==0)
    //               (- (t+|t|) if diagonal i in my j-range)
#define EPI_HS(AA, AB, HS)                                                     \
    {                                                                          \
        __syncthreads();   /* prev-hs combine done before Bex/Pex reuse */     \
        _Pragma("unroll")                                                      \
        for (int q = 0; q < 8; q++) Bex[(jbase + q) * 64 + hp] = AB[q];        \
        __syncthreads();                                                       \
        u64 sAp = AA[0];                                                       \
        _Pragma("unroll")                                                      \
        for (int q = 1; q < 8; q++) sAp = f2_add(sAp, AA[q]);                  \
        float2 sAf = f2_unpack(sAp);                                           \
        float SAm = sAf.x + sAf.y;                                             \
        u64 part[16];                                                          \
        _Pragma("unroll")                                                      \
        for (int i2 = 0; i2 < 16; i2++) {                                      \
            u64 Braw = Bex[i2 * 64 + hp];                                      \
            float2 B2 = f2_unpack(Braw);                                       \
            u64 bx = f2_pack(B2.x, B2.x), by = f2_pack(B2.y, B2.y);            \
            u64 ax = 0, ay = 0;                                                \
            _Pragma("unroll")                                                  \
            for (int q = 0; q < 8; q++) {                                      \
                u64 A = AA[q];                                                 \
                ax = f2_add(ax, f2_add(A, bx) & ABSM);                         \
                ay = f2_add(ay, f2_add(A, by) & ABSM);                         \
            }                                                                  \
            float2 axf = f2_unpack(ax), ayf = f2_unpack(ay);                   \
            float px = SAm + axf.x + axf.y;                                    \
            float py = SAm + ayf.x + ayf.y;                                    \
            if (jh == 0) { px = fmaf(32.f, B2.x, px); py = fmaf(32.f, B2.y, py); } \
            u64 p = f2_pack(px, py);                                           \
            if ((i2 >> 3) == jh) {                                             \
                u64 t = f2_add(AA[i2 & 7], Braw);                              \
                u64 d = f2_add(t, t & ABSM);                                   \
                p = f2_add(p, d ^ SIGN2);                                      \
            }                                                                  \
            part[i2] = p;                                                      \
        }                                                                      \
        if (jh == 1) {                                                         \
            _Pragma("unroll")                                                  \
            for (int i2 = 0; i2 < 16; i2++) Pex[i2 * 64 + hp] = part[i2];      \
        }                                                                      \
        __syncthreads();                                                       \
        if (jh == 0) {                                                         \
            _Pragma("unroll")                                                  \
            for (int i2 = 0; i2 < 16; i2++) {                                  \
                u64 tot = f2_add(part[i2], Pex[i2 * 64 + hp]);                 \
                *reinterpret_cast<u64*>(&PT[(h0 + HS) * PITCH + 2 * i2]) =     \
                    f2_mul(tot, HALF2);                                        \
            }                                                                  \
        }                                                                      \
    }

#define MSG_EPI(BM)                                                            \
    {                                                                          \
        float bb0 = (BM)[h0], bb1 = (BM)[h1];                                  \
        u64 bp0 = f2_pack(bb0, bb0), bp1 = f2_pack(bb1, bb1);                  \
        _Pragma("unroll")                                                      \
        for (int q = 0; q < 8; q++) {                                          \
            aA0[q] = f2_add(aA0[q], bp0);                                      \
            aA1[q] = f2_add(aA1[q], bp1);                                      \
        }                                                                      \
        EPI_HS(aA0, aB0, 0)                                                    \
        EPI_HS(aA1, aB1, 1)                                                    \
    }

    // ================= Layer 1 =================
    MSG_GEMM(g_Wt_msg1, DSA, xsT)
    MSG_EPI(bm1)
    __syncthreads();                 // PT(agg1) visible; Pex reads done before ws reuse

    UP_GEMM(g_Wt_up1)                // trailing sync: all reads of PT(agg1) done
    {
        float bb0 = bu1[h0], bb1 = bu1[h1];
        u64 bp0 = f2_pack(bb0, bb0), bp1 = f2_pack(bb1, bb1);
        #pragma unroll
        for (int q = 0; q < 8; q++) {
            float2 t0 = f2_unpack(f2_add(v0[q], bp0));
            float2 t1 = f2_unpack(f2_add(v1[q], bp1));
            *reinterpret_cast<u64*>(&PT[h0 * PITCH + ioff + 2 * q]) =
                f2_pack(fmaxf(t0.x, 0.f), fmaxf(t0.y, 0.f));
            *reinterpret_cast<u64*>(&PT[h1 * PITCH + ioff + 2 * q]) =
                f2_pack(fmaxf(t1.x, 0.f), fmaxf(t1.y, 0.f));
        }
    }
    __syncthreads();                 // PT(v1) visible

    // ================= Layer 2 =================
    MSG_GEMM(g_Wt_msg2, DH, PT)      // trailing sync: all reads of PT(v1) done
    MSG_EPI(bm2)
    __syncthreads();                 // PT(agg2) visible

    UP_GEMM(g_Wt_up2)
    {
        float bb0 = bu2[h0], bb1 = bu2[h1];
        u64 bp0 = f2_pack(bb0, bb0), bp1 = f2_pack(bb1, bb1);
        float m0 = -INFINITY, m1 = -INFINITY;
        #pragma unroll
        for (int q = 0; q < 8; q++) {
            float2 t0 = f2_unpack(f2_add(v0[q], bp0));
            float2 t1 = f2_unpack(f2_add(v1[q], bp1));
            m0 = fmaxf(m0, fmaxf(t0.x, t0.y));
            m1 = fmaxf(m1, fmaxf(t1.x, t1.y));
        }
        mxs[jh * DH + h0] = fmaxf(m0, 0.f);   // relu-then-max == max-then-relu
        mxs[jh * DH + h1] = fmaxf(m1, 0.f);
    }
    __syncthreads();

    // out[b] = sum_h max-over-i(v2[i][h]) * Wv[h] + bv
    float m = fmaxf(mxs[tid], mxs[DH + tid]);
    float contrib = m * Wv[tid];
    #pragma unroll
    for (int o = 16; o; o >>= 1)
        contrib += __shfl_xor_sync(0xffffffffu, contrib, o);
    if ((tid & 31) == 0) red[tid >> 5] = contrib;
    __syncthreads();
    if (tid == 0) out[b] = red[0] + red[1] + red[2] + red[3] + bv[0];
}

extern "C" void kernel_launch(void* const* d_in, const int* in_sizes, int n_in,
                              void* d_out, int out_size) {
    const float* x   = (const float*)d_in[0];
    // d_in[1] = ext_adj (structure folded into the agg epilogue)
    const float* Wm1 = (const float*)d_in[2];
    const float* bm1 = (const float*)d_in[3];
    const float* Wm2 = (const float*)d_in[4];
    const float* bm2 = (const float*)d_in[5];
    const float* Wu1 = (const float*)d_in[6];
    const float* bu1 = (const float*)d_in[7];
    const float* Wu2 = (const float*)d_in[8];
    const float* bu2 = (const float*)d_in[9];
    const float* Wv  = (const float*)d_in[10];
    const float* bv  = (const float*)d_in[11];

    prep_weights_kernel<<<148, 256>>>(Wm1, Wm2, Wu1, Wu2);
    msggraph_kernel<<<NB, 128>>>(x, bm1, bm2, bu1, bu2, Wv, bv, (float*)d_out);
}